// round 17
// baseline (speedup 1.0000x reference)
#include <cuda_runtime.h>
#include <cuda_bf16.h>
#include <cstdint>

// Problem constants
#define N_NODES 50000
#define E_EDGES 1600000
#define D_IN    64
#define HID     128
#define D_OUT   64
#define CAP     96      // per-node neighbor slot capacity (max degree ~58, 11-sigma)

// Device scratch (static globals; no runtime allocation)
__device__ __align__(16) float g_agg1[N_NODES * D_IN];      // 12.8 MB
__device__ __align__(16) float g_h1  [N_NODES * HID];       // 25.6 MB (fp32, gemm23 self-phase)
__device__ __align__(16) __nv_bfloat16 g_h1b[N_NODES * HID];// 12.8 MB (bf16, agg2 gather)
__device__ __align__(16) float g_agg2[N_NODES * HID];       // 25.6 MB
__device__ __align__(16) int   g_deg [N_NODES];
__device__ __align__(16) int   g_slots[N_NODES * CAP];      // 19.2 MB

// ---------------------------------------------------------------------------
// Helpers
// ---------------------------------------------------------------------------
__device__ __forceinline__ uint32_t f2tf(float f) {
    uint32_t u;
    asm("cvt.rna.tf32.f32 %0, %1;" : "=r"(u) : "f"(f));
    return u;
}

__device__ __forceinline__ float2 u32_to_f2(uint32_t u) {
    union { uint32_t u; __nv_bfloat162 h; } c; c.u = u;
    return __bfloat1622float2(c.h);
}

__device__ __forceinline__ void mma_tf32(float* c, const uint32_t* a,
                                         uint32_t b0, uint32_t b1) {
    asm volatile(
        "mma.sync.aligned.m16n8k8.row.col.f32.tf32.tf32.f32 "
        "{%0,%1,%2,%3}, {%4,%5,%6,%7}, {%8,%9}, {%0,%1,%2,%3};"
        : "+f"(c[0]), "+f"(c[1]), "+f"(c[2]), "+f"(c[3])
        : "r"(a[0]), "r"(a[1]), "r"(a[2]), "r"(a[3]), "r"(b0), "r"(b1));
}

// ---------------------------------------------------------------------------
// Single-pass neighbor bucketing, 8 edges/thread (MLP 8 over ATOMG latency)
// ---------------------------------------------------------------------------
__global__ void zero_deg_kernel() {
    int i = blockIdx.x * blockDim.x + threadIdx.x;
    if (i < N_NODES) g_deg[i] = 0;
}

__global__ void bucket_direct_kernel(const int* __restrict__ ei) {
    int t = blockIdx.x * blockDim.x + threadIdx.x;
    int e8 = t * 8;
    if (e8 >= E_EDGES) return;
    int4 sa = *(const int4*)(ei + e8);
    int4 sb = *(const int4*)(ei + e8 + 4);
    int4 da = *(const int4*)(ei + E_EDGES + e8);
    int4 db = *(const int4*)(ei + E_EDGES + e8 + 4);
    int s[8] = { sa.x, sa.y, sa.z, sa.w, sb.x, sb.y, sb.z, sb.w };
    int d[8] = { da.x, da.y, da.z, da.w, db.x, db.y, db.z, db.w };
    int pos[8];
#pragma unroll
    for (int q = 0; q < 8; q++) {
        if ((unsigned)s[q] < N_NODES && (unsigned)d[q] < N_NODES)
            pos[q] = atomicAdd(&g_deg[d[q]], 1);
        else
            pos[q] = -1;
    }
#pragma unroll
    for (int q = 0; q < 8; q++) {
        if (pos[q] >= 0) {
            if (pos[q] < CAP) g_slots[d[q] * CAP + pos[q]] = s[q];
            else              atomicSub(&g_deg[d[q]], 1);   // statistically unreachable
        }
    }
}

// ---------------------------------------------------------------------------
// Gather-aggregation: one warp per node. 32-bit addressing (all offsets <2^31).
// ---------------------------------------------------------------------------
__global__ void __launch_bounds__(256)
agg1_kernel(const float* __restrict__ x) {
    int w = (blockIdx.x * blockDim.x + threadIdx.x) >> 5;
    if (w >= N_NODES) return;
    int lane = threadIdx.x & 31;
    int deg = g_deg[w];
    const int* slots = g_slots + w * CAP;
    const float2* xb = (const float2*)x;
    float2 accA = make_float2(0.f, 0.f), accB = make_float2(0.f, 0.f);
    int j = 0;
    for (; j + 8 <= deg; j += 8) {
        int idx[8];
#pragma unroll
        for (int q = 0; q < 8; q++) idx[q] = slots[j + q] * 32 + lane;  // int32
        float2 v[8];
#pragma unroll
        for (int q = 0; q < 8; q++) v[q] = xb[idx[q]];
#pragma unroll
        for (int q = 0; q < 8; q += 2) {
            accA.x += v[q].x;     accA.y += v[q].y;
            accB.x += v[q + 1].x; accB.y += v[q + 1].y;
        }
    }
    for (; j < deg; j++) {
        float2 v = xb[slots[j] * 32 + lane];
        accA.x += v.x; accA.y += v.y;
    }
    float inv = 1.0f / fmaxf((float)deg, 1.0f);
    float2 acc = make_float2((accA.x + accB.x) * inv, (accA.y + accB.y) * inv);
    ((float2*)g_agg1)[w * 32 + lane] = acc;
}

__global__ void __launch_bounds__(256)
agg2_kernel() {
    int w = (blockIdx.x * blockDim.x + threadIdx.x) >> 5;
    if (w >= N_NODES) return;
    int lane = threadIdx.x & 31;
    int deg = g_deg[w];
    const int* slots = g_slots + w * CAP;
    const uint2* hb = (const uint2*)g_h1b;
    float4 accA = make_float4(0.f, 0.f, 0.f, 0.f);
    float4 accB = make_float4(0.f, 0.f, 0.f, 0.f);
    int j = 0;
    for (; j + 8 <= deg; j += 8) {
        int idx[8];
#pragma unroll
        for (int q = 0; q < 8; q++) idx[q] = slots[j + q] * 32 + lane;  // int32
        uint2 v[8];
#pragma unroll
        for (int q = 0; q < 8; q++) v[q] = hb[idx[q]];
#pragma unroll
        for (int q = 0; q < 8; q += 2) {
            float2 a0 = u32_to_f2(v[q].x);
            float2 a1 = u32_to_f2(v[q].y);
            float2 b0 = u32_to_f2(v[q + 1].x);
            float2 b1 = u32_to_f2(v[q + 1].y);
            accA.x += a0.x; accA.y += a0.y; accA.z += a1.x; accA.w += a1.y;
            accB.x += b0.x; accB.y += b0.y; accB.z += b1.x; accB.w += b1.y;
        }
    }
    for (; j < deg; j++) {
        uint2 v = hb[slots[j] * 32 + lane];
        float2 a0 = u32_to_f2(v.x);
        float2 a1 = u32_to_f2(v.y);
        accA.x += a0.x; accA.y += a0.y; accA.z += a1.x; accA.w += a1.y;
    }
    float inv = 1.0f / fmaxf((float)deg, 1.0f);
    float4 acc = make_float4((accA.x + accB.x) * inv, (accA.y + accB.y) * inv,
                             (accA.z + accB.z) * inv, (accA.w + accB.w) * inv);
    ((float4*)g_agg2)[w * 32 + lane] = acc;
}

// ---------------------------------------------------------------------------
// Tensor-core GEMM blocks (tf32 mma.sync.m16n8k8)
// Block tile 64 rows x 128 cols, 8 warps 2(m) x 4(n): warp tile 32x32.
// acc = 32 regs/thread -> 3 CTAs/SM (24 warps) for latency hiding.
// ---------------------------------------------------------------------------
#define SA_STRIDE 36
#define SW_STRIDE 136
#define SA_U32 (64 * SA_STRIDE)    // 2304
#define SW_U32 (32 * SW_STRIDE)    // 4352

// Fill sA chunk: 64 rows, 32 k. 512 uint4 total -> 2 per thread.
template<int K>
__device__ __forceinline__ void fill_sA64(uint32_t* sA, const float* A,
                                          int r0, int k0, int tid) {
#pragma unroll
    for (int u = 0; u < 2; u++) {
        int i = tid + u * 256;
        int row = i >> 3, kq = i & 7;
        int r = r0 + row;
        float4 v = (r < N_NODES)
            ? *(const float4*)(A + (size_t)r * K + k0 + kq * 4)
            : make_float4(0.f, 0.f, 0.f, 0.f);
        *(uint4*)&sA[row * SA_STRIDE + kq * 4] =
            make_uint4(f2tf(v.x), f2tf(v.y), f2tf(v.z), f2tf(v.w));
    }
}

__device__ __forceinline__ void fill_sW(uint32_t* sW, const float* W,
                                        int k0, int tid) {
#pragma unroll
    for (int u = 0; u < 4; u++) {
        int i = tid + u * 256;
        int k = i >> 5, n4 = (i & 31) * 4;
        float4 v = *(const float4*)(W + (size_t)(k0 + k) * HID + n4);
        *(uint4*)&sW[k * SW_STRIDE + n4] =
            make_uint4(f2tf(v.x), f2tf(v.y), f2tf(v.z), f2tf(v.w));
    }
}

// Warp-tile 32x32 MMA over one 32-k chunk
__device__ __forceinline__ void mma_chunk32(float (*acc)[4][4],
                                            const uint32_t* sA, const uint32_t* sW,
                                            int m0, int n0, int g, int tg) {
#pragma unroll
    for (int kk = 0; kk < 32; kk += 8) {
        uint32_t a[2][4];
#pragma unroll
        for (int mf = 0; mf < 2; mf++) {
            int rb = m0 + mf * 16;
            a[mf][0] = sA[(rb + g)     * SA_STRIDE + kk + tg];
            a[mf][1] = sA[(rb + g + 8) * SA_STRIDE + kk + tg];
            a[mf][2] = sA[(rb + g)     * SA_STRIDE + kk + tg + 4];
            a[mf][3] = sA[(rb + g + 8) * SA_STRIDE + kk + tg + 4];
        }
#pragma unroll
        for (int nf = 0; nf < 4; nf++) {
            int nb = n0 + nf * 8 + g;
            uint32_t b0 = sW[(kk + tg)     * SW_STRIDE + nb];
            uint32_t b1 = sW[(kk + tg + 4) * SW_STRIDE + nb];
            mma_tf32(acc[0][nf], a[0], b0, b1);
            mma_tf32(acc[1][nf], a[1], b0, b1);
        }
    }
}

// ---------------------------------------------------------------------------
// Layer-1: h1 = relu(agg1@Wl1 + x@Wr1 + b1). BR=64, grid 782, occ 3.
// ---------------------------------------------------------------------------
#define SMEM1_U32 (SA_U32 + SW_U32)

__global__ void __launch_bounds__(256, 3)
gemm1_kernel(const float* __restrict__ xin,
             const float* __restrict__ Wl,
             const float* __restrict__ Wr,
             const float* __restrict__ bias)
{
    extern __shared__ uint32_t smem[];
    uint32_t* sA = smem;
    uint32_t* sW = smem + SA_U32;

    const int tid  = threadIdx.x;
    const int wid  = tid >> 5;
    const int lane = tid & 31;
    const int g    = lane >> 2;
    const int tg   = lane & 3;
    const int m0   = (wid & 1) * 32;
    const int n0   = (wid >> 1) * 32;
    const int r0   = blockIdx.x * 64;

    float acc[2][4][4];
#pragma unroll
    for (int mf = 0; mf < 2; mf++)
#pragma unroll
        for (int nf = 0; nf < 4; nf++)
#pragma unroll
            for (int q = 0; q < 4; q++) acc[mf][nf][q] = 0.f;

#pragma unroll 1
    for (int ph = 0; ph < 2; ph++) {
        const float* A = (ph == 0) ? g_agg1 : xin;
        const float* W = (ph == 0) ? Wl : Wr;
#pragma unroll 1
        for (int k0 = 0; k0 < D_IN; k0 += 32) {
            __syncthreads();
            fill_sA64<D_IN>(sA, A, r0, k0, tid);
            fill_sW(sW, W, k0, tid);
            __syncthreads();
            mma_chunk32(acc, sA, sW, m0, n0, g, tg);
        }
    }

    // Epilogue: bias + relu -> g_h1 (fp32) + g_h1b (bf16)
#pragma unroll
    for (int mf = 0; mf < 2; mf++) {
        int rbase = r0 + m0 + mf * 16;
#pragma unroll
        for (int nf = 0; nf < 4; nf++) {
            int c = n0 + nf * 8 + 2 * tg;
            float b0 = bias[c], b1 = bias[c + 1];
            int ra = rbase + g, rb = rbase + g + 8;
            if (ra < N_NODES) {
                float2 v = make_float2(fmaxf(acc[mf][nf][0] + b0, 0.f),
                                       fmaxf(acc[mf][nf][1] + b1, 0.f));
                *(float2*)(g_h1 + (size_t)ra * HID + c) = v;
                *(__nv_bfloat162*)(g_h1b + (size_t)ra * HID + c) = __float22bfloat162_rn(v);
            }
            if (rb < N_NODES) {
                float2 v = make_float2(fmaxf(acc[mf][nf][2] + b0, 0.f),
                                       fmaxf(acc[mf][nf][3] + b1, 0.f));
                *(float2*)(g_h1 + (size_t)rb * HID + c) = v;
                *(__nv_bfloat162*)(g_h1b + (size_t)rb * HID + c) = __float22bfloat162_rn(v);
            }
        }
    }
}

// ---------------------------------------------------------------------------
// Fused layers 2+3, BR=64, occ 3:
//   h2 = relu(agg2@Wl2 + h1@Wr2 + b2)  staged in SMEM tf32 (64 rows)
//   out = h2 @ Wo + bo
// smem: [region0: max(sA+sW, sWoT)=8448][sH2: 64*132=8448] = 67584 B.
// ---------------------------------------------------------------------------
#define SH2_STRIDE 132
#define SWO_STRIDE 132
#define REGION0_U32 8448            // >= SA_U32+SW_U32 (6656), == 64*SWO_STRIDE
#define SMEM23_U32 (REGION0_U32 + 64 * SH2_STRIDE)

__global__ void __launch_bounds__(256, 3)
gemm23_kernel(const float* __restrict__ Wl,
              const float* __restrict__ Wr,
              const float* __restrict__ bias2,
              const float* __restrict__ Wo,
              const float* __restrict__ biasO,
              float* __restrict__ outp)
{
    extern __shared__ uint32_t smem[];
    uint32_t* sA   = smem;
    uint32_t* sW   = smem + SA_U32;
    uint32_t* sWoT = smem;                   // union with sA+sW (phase B)
    uint32_t* sH2  = smem + REGION0_U32;     // 64*132

    const int tid  = threadIdx.x;
    const int wid  = tid >> 5;
    const int lane = tid & 31;
    const int g    = lane >> 2;
    const int tg   = lane & 3;
    const int m0   = (wid & 1) * 32;
    const int n0   = (wid >> 1) * 32;
    const int r0   = blockIdx.x * 64;

    float acc[2][4][4];
#pragma unroll
    for (int mf = 0; mf < 2; mf++)
#pragma unroll
        for (int nf = 0; nf < 4; nf++)
#pragma unroll
            for (int q = 0; q < 4; q++) acc[mf][nf][q] = 0.f;

#pragma unroll 1
    for (int ph = 0; ph < 2; ph++) {
        const float* A = (ph == 0) ? g_agg2 : g_h1;
        const float* W = (ph == 0) ? Wl : Wr;
#pragma unroll 1
        for (int k0 = 0; k0 < HID; k0 += 32) {
            __syncthreads();
            fill_sA64<HID>(sA, A, r0, k0, tid);
            fill_sW(sW, W, k0, tid);
            __syncthreads();
            mma_chunk32(acc, sA, sW, m0, n0, g, tg);
        }
    }

    // Stage h2 = relu(acc + b2) into sH2 as tf32 bits (local rows 0..63)
#pragma unroll
    for (int mf = 0; mf < 2; mf++) {
        int rbase = m0 + mf * 16;
#pragma unroll
        for (int nf = 0; nf < 4; nf++) {
            int c = n0 + nf * 8 + 2 * tg;
            float b0 = bias2[c], b1 = bias2[c + 1];
            sH2[(rbase + g) * SH2_STRIDE + c]         = f2tf(fmaxf(acc[mf][nf][0] + b0, 0.f));
            sH2[(rbase + g) * SH2_STRIDE + c + 1]     = f2tf(fmaxf(acc[mf][nf][1] + b1, 0.f));
            sH2[(rbase + g + 8) * SH2_STRIDE + c]     = f2tf(fmaxf(acc[mf][nf][2] + b0, 0.f));
            sH2[(rbase + g + 8) * SH2_STRIDE + c + 1] = f2tf(fmaxf(acc[mf][nf][3] + b1, 0.f));
        }
    }
    __syncthreads();   // sH2 complete; sA/sW reads done -> safe to overwrite

    // Fill sWoT[n][k] = tf32(Wo[k][n])   (Wo: 128 x 64 row-major)
#pragma unroll
    for (int i = tid; i < HID * D_OUT; i += 256) {
        int k = i >> 6;
        int n = i & 63;
        sWoT[n * SWO_STRIDE + k] = f2tf(Wo[i]);
    }
    __syncthreads();

    // Phase B: out = sH2 @ Wo + bo   (64 x 64, K=128). Warp tile 32x16.
    {
        const int n0b = (wid >> 1) * 16;
        float acc2[2][2][4];
#pragma unroll
        for (int mf = 0; mf < 2; mf++)
#pragma unroll
            for (int nf = 0; nf < 2; nf++)
#pragma unroll
                for (int q = 0; q < 4; q++) acc2[mf][nf][q] = 0.f;

#pragma unroll 4
        for (int kk = 0; kk < HID; kk += 8) {
            uint32_t a[2][4];
#pragma unroll
            for (int mf = 0; mf < 2; mf++) {
                int rb = m0 + mf * 16;
                a[mf][0] = sH2[(rb + g)     * SH2_STRIDE + kk + tg];
                a[mf][1] = sH2[(rb + g + 8) * SH2_STRIDE + kk + tg];
                a[mf][2] = sH2[(rb + g)     * SH2_STRIDE + kk + tg + 4];
                a[mf][3] = sH2[(rb + g + 8) * SH2_STRIDE + kk + tg + 4];
            }
#pragma unroll
            for (int nf = 0; nf < 2; nf++) {
                int nb = n0b + nf * 8 + g;
                uint32_t b0 = sWoT[nb * SWO_STRIDE + kk + tg];
                uint32_t b1 = sWoT[nb * SWO_STRIDE + kk + tg + 4];
                mma_tf32(acc2[0][nf], a[0], b0, b1);
                mma_tf32(acc2[1][nf], a[1], b0, b1);
            }
        }

#pragma unroll
        for (int mf = 0; mf < 2; mf++) {
            int rbase = r0 + m0 + mf * 16;
#pragma unroll
            for (int nf = 0; nf < 2; nf++) {
                int c = n0b + nf * 8 + 2 * tg;
                float b0 = biasO[c], b1 = biasO[c + 1];
                int ra = rbase + g, rb = rbase + g + 8;
                if (ra < N_NODES) {
                    float2 v = make_float2(acc2[mf][nf][0] + b0,
                                           acc2[mf][nf][1] + b1);
                    *(float2*)(outp + (size_t)ra * D_OUT + c) = v;
                }
                if (rb < N_NODES) {
                    float2 v = make_float2(acc2[mf][nf][2] + b0,
                                           acc2[mf][nf][3] + b1);
                    *(float2*)(outp + (size_t)rb * D_OUT + c) = v;
                }
            }
        }
    }
}

// ---------------------------------------------------------------------------
// Launch
// ---------------------------------------------------------------------------
extern "C" void kernel_launch(void* const* d_in, const int* in_sizes, int n_in,
                              void* d_out, int out_size) {
    const float* x   = (const float*)d_in[0];
    const int*   ei  = (const int*)d_in[1];   // int32 (JAX default demotion)
    const float* Wl1 = (const float*)d_in[2];
    const float* b1  = (const float*)d_in[3];
    const float* Wr1 = (const float*)d_in[4];
    const float* Wl2 = (const float*)d_in[5];
    const float* b2  = (const float*)d_in[6];
    const float* Wr2 = (const float*)d_in[7];
    const float* Wo  = (const float*)d_in[8];
    const float* bo  = (const float*)d_in[9];
    float* out = (float*)d_out;

    cudaFuncSetAttribute(gemm1_kernel,
                         cudaFuncAttributeMaxDynamicSharedMemorySize,
                         SMEM1_U32 * 4);
    cudaFuncSetAttribute(gemm23_kernel,
                         cudaFuncAttributeMaxDynamicSharedMemorySize,
                         SMEM23_U32 * 4);

    // Single-pass neighbor-list build
    zero_deg_kernel<<<(N_NODES + 255) / 256, 256>>>();
    bucket_direct_kernel<<<(E_EDGES / 8 + 255) / 256, 256>>>(ei);

    constexpr int WGRID = (N_NODES * 32 + 255) / 256;   // warp-per-node grids
    constexpr int GB64  = (N_NODES + 63) / 64;          // 782

    agg1_kernel<<<WGRID, 256>>>(x);
    gemm1_kernel<<<GB64, 256, SMEM1_U32 * 4>>>(x, Wl1, Wr1, b1);

    agg2_kernel<<<WGRID, 256>>>();
    gemm23_kernel<<<GB64, 256, SMEM23_U32 * 4>>>(Wl2, Wr2, b2, Wo, bo, out);
}